// round 13
// baseline (speedup 1.0000x reference)
#include <cuda_runtime.h>
#include <cuda_bf16.h>
#include <cuda_fp16.h>
#include <cstdint>
#include <cstddef>

#define NQ  4096
#define EMB 768
#define HID 1024
#define MEM 65536
#define KSPLIT 4
#define BM 128
#define BN 256
#define NT_LOGITS (MEM / BN)   // 256 n-tiles in logits GEMM

// ---------------- static device scratch ----------------
__device__ __nv_bfloat16 g_qh[NQ*EMB],        g_ql[NQ*EMB];
__device__ __nv_bfloat16 g_Winh[HID*EMB],     g_Winl[HID*EMB];      // weights transposed: [N][K]
__device__ __nv_bfloat16 g_We1h[2*HID*HID],   g_We1l[2*HID*HID];
__device__ __nv_bfloat16 g_We2h[HID*2*HID],   g_We2l[HID*2*HID];
__device__ __nv_bfloat16 g_Wkh[HID*HID],      g_Wkl[HID*HID];
__device__ __nv_bfloat16 g_Wr1h[2*HID*2*HID], g_Wr1l[2*HID*2*HID];
__device__ __nv_bfloat16 g_Wr2h[EMB*2*HID],   g_Wr2l[EMB*2*HID];
__device__ __nv_bfloat16 g_xh[NQ*HID],   g_xl[NQ*HID];
__device__ __nv_bfloat16 g_hh[NQ*2*HID], g_hl[NQ*2*HID];
__device__ __nv_bfloat16 g_ch[NQ*2*HID], g_cl[NQ*2*HID];   // combined = [encoded | retrieved]
__device__ __nv_bfloat16 g_key[NQ*HID];
__device__ __nv_bfloat16 g_rh[NQ*2*HID], g_rl[NQ*2*HID];
// int8 attention path
__device__ int8_t  g_key8[NQ*HID];
__device__ float   g_sk[NQ];                       // key per-row scale (amax/127)
__device__ int8_t  g_MK8[(size_t)MEM*HID];         // mem_keys int8 [MEM][HID] = [N][K]
__device__ float   g_skb[MEM];                     // mem_keys per-row scale
__device__ int8_t  g_MVT8[(size_t)HID*MEM];        // mem_values^T int8 [HID][MEM] = [N][K]
__device__ int     g_svi[HID];                     // per-HID-col amax of values (float bits)
__device__ __half  g_L[(size_t)NQ*MEM];            // scaled logits fp16 (512MB)
__device__ int8_t  g_P8[(size_t)NQ*MEM];           // P int8 = rn(127*exp(l-rowmax)) (256MB)
__device__ float   g_part[(size_t)KSPLIT*NQ*HID];  // split-K partials
__device__ float   g_prs[(size_t)NQ*NT_LOGITS];    // per-tile rowmax partials
__device__ float   g_rowmax[NQ];
__device__ float   g_rs[NQ];                       // rowsum = sum of q (integer, exact)

// ---------------- helpers ----------------
__device__ __forceinline__ void cpasync16(uint32_t saddr, const void* g) {
    asm volatile("cp.async.cg.shared.global [%0], [%1], 16;\n" :: "r"(saddr), "l"(g));
}
__device__ __forceinline__ void ldsm4(uint32_t* r, uint32_t addr) {
    asm volatile("ldmatrix.sync.aligned.m8n8.x4.shared.b16 {%0,%1,%2,%3}, [%4];\n"
        : "=r"(r[0]), "=r"(r[1]), "=r"(r[2]), "=r"(r[3]) : "r"(addr));
}
__device__ __forceinline__ void mma_bf16(float* c, const uint32_t* a, uint32_t b0, uint32_t b1) {
    asm volatile(
        "mma.sync.aligned.m16n8k16.row.col.f32.bf16.bf16.f32 "
        "{%0,%1,%2,%3}, {%4,%5,%6,%7}, {%8,%9}, {%0,%1,%2,%3};\n"
        : "+f"(c[0]), "+f"(c[1]), "+f"(c[2]), "+f"(c[3])
        : "r"(a[0]), "r"(a[1]), "r"(a[2]), "r"(a[3]), "r"(b0), "r"(b1));
}
__device__ __forceinline__ void mma_s8(int* c, const uint32_t* a, uint32_t b0, uint32_t b1) {
    asm volatile(
        "mma.sync.aligned.m16n8k32.row.col.s32.s8.s8.s32 "
        "{%0,%1,%2,%3}, {%4,%5,%6,%7}, {%8,%9}, {%0,%1,%2,%3};\n"
        : "+r"(c[0]), "+r"(c[1]), "+r"(c[2]), "+r"(c[3])
        : "r"(a[0]), "r"(a[1]), "r"(a[2]), "r"(a[3]), "r"(b0), "r"(b1));
}
__device__ __forceinline__ float gelu_erf(float x) {
    return 0.5f * x * (1.0f + erff(x * 0.70710678118654752f));
}
__device__ __forceinline__ uint32_t pack_bf2(float a, float b) {
    __nv_bfloat162 h; h.x = __float2bfloat16(a); h.y = __float2bfloat16(b);
    return *reinterpret_cast<uint32_t*>(&h);
}

// ======================= bf16 split HMMA GEMM (small main-path GEMMs) ===============
// C[M,N] = A[M,K] @ B[N,K]^T, 3-product hi/lo bf16 split, BK=32, 4 stages.
// EPI: 0 (+bias?)->f32 | 1 +bias->hi/lo bf16 | 2 +bias,gelu->hi/lo | 3 +bias->bf16
template<int EPI>
__global__ void __launch_bounds__(512, 1) gemm_hmma(
    const __nv_bfloat16* __restrict__ Ah, const __nv_bfloat16* __restrict__ Al,
    const __nv_bfloat16* __restrict__ Bh, const __nv_bfloat16* __restrict__ Bl,
    const float* __restrict__ bias,
    float* __restrict__ outF, __nv_bfloat16* __restrict__ outHi, __nv_bfloat16* __restrict__ outLo,
    int K, int lda, int ldb, int ldc)
{
    constexpr int NST = 4, PRE = 3, SST = 49152;
    extern __shared__ char smem[];
    const uint32_t sb = (uint32_t)__cvta_generic_to_shared(smem);
    const int tid = threadIdx.x;
    const int lane = tid & 31, wid = tid >> 5;
    const int wm = wid & 1, wn = wid >> 1;
    const int m0 = blockIdx.x * BM;
    const int n0 = blockIdx.y * BN;

    float acc[4][4][4];
    #pragma unroll
    for (int i = 0; i < 4; i++)
        #pragma unroll
        for (int j = 0; j < 4; j++)
            #pragma unroll
            for (int q = 0; q < 4; q++) acc[i][j][q] = 0.f;

    const int nkb = K >> 5;

    auto LOAD = [&](int st, int kb) {
        const uint32_t base = sb + st * SST;
        const size_t kg = (size_t)kb * 32;
        {
            int row = tid >> 2, c = tid & 3;
            uint32_t so = base + row * 64 + ((c ^ ((row >> 1) & 3)) << 4);
            const size_t go = (size_t)(m0 + row) * lda + kg + c * 8;
            cpasync16(so, Ah + go);
            cpasync16(so + 24576, Al + go);
        }
        #pragma unroll
        for (int i = 0; i < 2; i++) {
            int id = tid + i * 512;
            int row = id >> 2, c = id & 3;
            uint32_t so = base + 8192 + row * 64 + ((c ^ ((row >> 1) & 3)) << 4);
            const size_t go = (size_t)(n0 + row) * ldb + kg + c * 8;
            cpasync16(so, Bh + go);
            cpasync16(so + 24576, Bl + go);
        }
        asm volatile("cp.async.commit_group;" ::);
    };

    const int amat = lane >> 3;
    const int arow_l = (amat & 1) * 8 + (lane & 7);
    const int achv   = amat >> 1;
    const int brow_l = (amat >> 1) * 8 + (lane & 7);
    const int bchv   = amat & 1;

    auto COMPUTE = [&](int st) {
        const uint32_t ab = sb + st * SST;
        const uint32_t bb = ab + 8192;
        #pragma unroll
        for (int t = 0; t < 2; t++) {
            uint32_t ah[4][4], bh[2][4];
            #pragma unroll
            for (int mi = 0; mi < 4; mi++) {
                int row = wm * 64 + mi * 16 + arow_l;
                int ch = 2 * t + achv;
                ldsm4(ah[mi], ab + row * 64 + ((ch ^ ((row >> 1) & 3)) << 4));
            }
            #pragma unroll
            for (int nb = 0; nb < 2; nb++) {
                int row = wn * 32 + nb * 16 + brow_l;
                int ch = 2 * t + bchv;
                ldsm4(bh[nb], bb + row * 64 + ((ch ^ ((row >> 1) & 3)) << 4));
            }
            #pragma unroll
            for (int mi = 0; mi < 4; mi++)
                #pragma unroll
                for (int ni = 0; ni < 4; ni++)
                    mma_bf16(acc[mi][ni], ah[mi],
                             bh[ni >> 1][(ni & 1) * 2], bh[ni >> 1][(ni & 1) * 2 + 1]);
            {
                uint32_t al[4][4];
                #pragma unroll
                for (int mi = 0; mi < 4; mi++) {
                    int row = wm * 64 + mi * 16 + arow_l;
                    int ch = 2 * t + achv;
                    ldsm4(al[mi], ab + 24576 + row * 64 + ((ch ^ ((row >> 1) & 3)) << 4));
                }
                #pragma unroll
                for (int mi = 0; mi < 4; mi++)
                    #pragma unroll
                    for (int ni = 0; ni < 4; ni++)
                        mma_bf16(acc[mi][ni], al[mi],
                                 bh[ni >> 1][(ni & 1) * 2], bh[ni >> 1][(ni & 1) * 2 + 1]);
            }
            {
                uint32_t bl[2][4];
                #pragma unroll
                for (int nb = 0; nb < 2; nb++) {
                    int row = wn * 32 + nb * 16 + brow_l;
                    int ch = 2 * t + bchv;
                    ldsm4(bl[nb], bb + 24576 + row * 64 + ((ch ^ ((row >> 1) & 3)) << 4));
                }
                #pragma unroll
                for (int mi = 0; mi < 4; mi++)
                    #pragma unroll
                    for (int ni = 0; ni < 4; ni++)
                        mma_bf16(acc[mi][ni], ah[mi],
                                 bl[ni >> 1][(ni & 1) * 2], bl[ni >> 1][(ni & 1) * 2 + 1]);
            }
        }
    };

    #pragma unroll
    for (int i = 0; i < PRE; i++) LOAD(i, i);
    for (int kb = 0; kb < nkb; kb++) {
        const int pend = (nkb - kb < PRE) ? (nkb - kb) : PRE;
        if (pend == 3)      asm volatile("cp.async.wait_group 2;" ::: "memory");
        else if (pend == 2) asm volatile("cp.async.wait_group 1;" ::: "memory");
        else                asm volatile("cp.async.wait_group 0;" ::: "memory");
        __syncthreads();
        COMPUTE(kb % NST);
        if (kb + PRE < nkb) LOAD((kb + PRE) % NST, kb + PRE);
    }
    __syncthreads();

    // epilogue via SMEM stage
    float* smf = reinterpret_cast<float*>(smem);
    #pragma unroll
    for (int mi = 0; mi < 4; mi++)
        #pragma unroll
        for (int ni = 0; ni < 4; ni++) {
            int r = wm * 64 + mi * 16 + (lane >> 2);
            int cc = wn * 32 + ni * 8 + (lane & 3) * 2;
            smf[r * 258 + cc]           = acc[mi][ni][0];
            smf[r * 258 + cc + 1]       = acc[mi][ni][1];
            smf[(r + 8) * 258 + cc]     = acc[mi][ni][2];
            smf[(r + 8) * 258 + cc + 1] = acc[mi][ni][3];
        }
    __syncthreads();
    {
        const int r = tid & 127, sg = tid >> 7;
        const float* srow = smf + r * 258 + sg * 64;
        const int colbase = n0 + sg * 64;
        float v[64];
        #pragma unroll
        for (int j = 0; j < 64; j++) {
            float x = srow[j];
            if (EPI >= 1 || bias != nullptr) x += __ldg(bias + colbase + j);
            if (EPI == 2) x = gelu_erf(x);
            v[j] = x;
        }
        const size_t gb = (size_t)(m0 + r) * ldc + colbase;
        if (EPI == 0) {
            #pragma unroll
            for (int j = 0; j < 64; j += 4)
                *reinterpret_cast<float4*>(outF + gb + j) =
                    make_float4(v[j], v[j+1], v[j+2], v[j+3]);
        } else if (EPI == 3) {
            #pragma unroll
            for (int j = 0; j < 64; j += 8) {
                uint4 u;
                u.x = pack_bf2(v[j+0], v[j+1]); u.y = pack_bf2(v[j+2], v[j+3]);
                u.z = pack_bf2(v[j+4], v[j+5]); u.w = pack_bf2(v[j+6], v[j+7]);
                *reinterpret_cast<uint4*>(outHi + gb + j) = u;
            }
        } else {
            #pragma unroll
            for (int j = 0; j < 64; j += 8) {
                float lo[8];
                #pragma unroll
                for (int q = 0; q < 8; q++) {
                    __nv_bfloat16 hb = __float2bfloat16(v[j + q]);
                    lo[q] = v[j + q] - __bfloat162float(hb);
                }
                uint4 uh, ul;
                uh.x = pack_bf2(v[j+0], v[j+1]); uh.y = pack_bf2(v[j+2], v[j+3]);
                uh.z = pack_bf2(v[j+4], v[j+5]); uh.w = pack_bf2(v[j+6], v[j+7]);
                ul.x = pack_bf2(lo[0], lo[1]);   ul.y = pack_bf2(lo[2], lo[3]);
                ul.z = pack_bf2(lo[4], lo[5]);   ul.w = pack_bf2(lo[6], lo[7]);
                *reinterpret_cast<uint4*>(outHi + gb + j) = uh;
                *reinterpret_cast<uint4*>(outLo + gb + j) = ul;
            }
        }
    }
}

// ======================= INT8 IMMA GEMM (attention GEMMs) =======================
// C_i32[M,N] = A_s8[M,K] @ B_s8[N,K]^T.  BK = 64 bytes, 4 stages of 24KB.
// EPI 0 (logits): l = i32*ska[r]*skb[c]*(1/32) -> fp16 out + per-tile rowmax partials
// EPI 1 (retrieved partial): out_f32 = i32 * skb[c] * (1/127); paired with rs = sum(q_P)
//       so that part/rs = i32*amax_v/(127*sum q_P) = true attn-weighted value.
// SWAP: n-tile fastest.
template<int EPI, bool SWAP>
__global__ void __launch_bounds__(512, 1) gemm_i8(
    const int8_t* __restrict__ A, const int8_t* __restrict__ B,
    const float* __restrict__ ska, const float* __restrict__ skb,
    __half* __restrict__ outL, float* __restrict__ outF, float* __restrict__ prs,
    int K, int lda, int ldb, int ldc, size_t zstride)
{
    constexpr int NST = 4, PRE = 3, SST = 24576;
    extern __shared__ char smem[];
    const uint32_t sb = (uint32_t)__cvta_generic_to_shared(smem);
    const int tid = threadIdx.x;
    const int lane = tid & 31, wid = tid >> 5;
    const int wm = wid & 1, wn = wid >> 1;
    const int m0 = (SWAP ? blockIdx.y : blockIdx.x) * BM;
    const int n0 = (SWAP ? blockIdx.x : blockIdx.y) * BN;
    const int ntile = SWAP ? blockIdx.x : blockIdx.y;
    const size_t kz = (size_t)blockIdx.z * K;
    outF += (size_t)blockIdx.z * zstride;

    int acc[4][4][4];
    #pragma unroll
    for (int i = 0; i < 4; i++)
        #pragma unroll
        for (int j = 0; j < 4; j++)
            #pragma unroll
            for (int q = 0; q < 4; q++) acc[i][j][q] = 0;

    const int nkb = K >> 6;   // BK = 64 bytes

    auto LOAD = [&](int st, int kb) {
        const uint32_t base = sb + st * SST;
        const size_t kg = kz + (size_t)kb * 64;
        {   // A: 128 rows x 4 chunks of 16B
            int row = tid >> 2, c = tid & 3;
            uint32_t so = base + row * 64 + ((c ^ ((row >> 1) & 3)) << 4);
            cpasync16(so, A + (size_t)(m0 + row) * lda + kg + c * 16);
        }
        #pragma unroll
        for (int i = 0; i < 2; i++) {   // B: 256 rows x 4 chunks
            int id = tid + i * 512;
            int row = id >> 2, c = id & 3;
            uint32_t so = base + 8192 + row * 64 + ((c ^ ((row >> 1) & 3)) << 4);
            cpasync16(so, B + (size_t)(n0 + row) * ldb + kg + c * 16);
        }
        asm volatile("cp.async.commit_group;" ::);
    };

    const int amat = lane >> 3;
    const int arow_l = (amat & 1) * 8 + (lane & 7);
    const int achv   = amat >> 1;
    const int brow_l = (amat >> 1) * 8 + (lane & 7);
    const int bchv   = amat & 1;

    auto COMPUTE = [&](int st) {
        const uint32_t ab = sb + st * SST;
        const uint32_t bb = ab + 8192;
        #pragma unroll
        for (int t = 0; t < 2; t++) {   // two k32 steps per 64B block
            uint32_t a[4][4], b[2][4];
            #pragma unroll
            for (int mi = 0; mi < 4; mi++) {
                int row = wm * 64 + mi * 16 + arow_l;
                int ch = 2 * t + achv;
                ldsm4(a[mi], ab + row * 64 + ((ch ^ ((row >> 1) & 3)) << 4));
            }
            #pragma unroll
            for (int nb = 0; nb < 2; nb++) {
                int row = wn * 32 + nb * 16 + brow_l;
                int ch = 2 * t + bchv;
                ldsm4(b[nb], bb + row * 64 + ((ch ^ ((row >> 1) & 3)) << 4));
            }
            #pragma unroll
            for (int mi = 0; mi < 4; mi++)
                #pragma unroll
                for (int ni = 0; ni < 4; ni++)
                    mma_s8(acc[mi][ni], a[mi],
                           b[ni >> 1][(ni & 1) * 2], b[ni >> 1][(ni & 1) * 2 + 1]);
        }
    };

    #pragma unroll
    for (int i = 0; i < PRE; i++) LOAD(i, i);
    for (int kb = 0; kb < nkb; kb++) {
        const int pend = (nkb - kb < PRE) ? (nkb - kb) : PRE;
        if (pend == 3)      asm volatile("cp.async.wait_group 2;" ::: "memory");
        else if (pend == 2) asm volatile("cp.async.wait_group 1;" ::: "memory");
        else                asm volatile("cp.async.wait_group 0;" ::: "memory");
        __syncthreads();
        COMPUTE(kb % NST);
        if (kb + PRE < nkb) LOAD((kb + PRE) % NST, kb + PRE);
    }
    __syncthreads();

    // epilogue: stage raw i32 (as float) + per-tile col scales, then scale + out
    float* smf = reinterpret_cast<float*>(smem);
    float* redbuf = smf + 128 * 258;        // 512
    float* skbs   = redbuf + 512;           // 256 col scales
    #pragma unroll
    for (int mi = 0; mi < 4; mi++)
        #pragma unroll
        for (int ni = 0; ni < 4; ni++) {
            int r = wm * 64 + mi * 16 + (lane >> 2);
            int cc = wn * 32 + ni * 8 + (lane & 3) * 2;
            smf[r * 258 + cc]           = (float)acc[mi][ni][0];
            smf[r * 258 + cc + 1]       = (float)acc[mi][ni][1];
            smf[(r + 8) * 258 + cc]     = (float)acc[mi][ni][2];
            smf[(r + 8) * 258 + cc + 1] = (float)acc[mi][ni][3];
        }
    if (tid < 256) skbs[tid] = __ldg(skb + n0 + tid);
    __syncthreads();
    {
        const int r = tid & 127, sg = tid >> 7;
        const float* srow = smf + r * 258 + sg * 64;
        const float* scl  = skbs + sg * 64;
        const size_t gb = (size_t)(m0 + r) * ldc + n0 + sg * 64;
        if (EPI == 0) {
            const float sa = __ldg(ska + m0 + r) * 0.03125f;   // fold 1/sqrt(HID)=1/32
            float mx = -1e30f;
            #pragma unroll
            for (int j = 0; j < 64; j += 8) {
                __half2 hp[4];
                #pragma unroll
                for (int q = 0; q < 4; q++) {
                    float l0 = srow[j + 2*q]     * sa * scl[j + 2*q];
                    float l1 = srow[j + 2*q + 1] * sa * scl[j + 2*q + 1];
                    mx = fmaxf(mx, fmaxf(l0, l1));
                    hp[q] = __floats2half2_rn(l0, l1);
                }
                *reinterpret_cast<uint4*>(outL + gb + j) =
                    *reinterpret_cast<uint4*>(hp);
            }
            redbuf[sg * 128 + r] = mx;
        } else {
            #pragma unroll
            for (int j = 0; j < 64; j += 4) {
                float4 f;
                f.x = srow[j+0] * scl[j+0] * (1.f/127.f);
                f.y = srow[j+1] * scl[j+1] * (1.f/127.f);
                f.z = srow[j+2] * scl[j+2] * (1.f/127.f);
                f.w = srow[j+3] * scl[j+3] * (1.f/127.f);
                *reinterpret_cast<float4*>(outF + gb + j) = f;
            }
        }
    }
    if (EPI == 0) {
        __syncthreads();
        if (tid < 128) {
            float m = fmaxf(fmaxf(redbuf[tid], redbuf[128 + tid]),
                            fmaxf(redbuf[256 + tid], redbuf[384 + tid]));
            prs[(size_t)(m0 + tid) * NT_LOGITS + ntile] = m;
        }
    }
}

// ---------------- conversion / quant / reduction kernels ----------------
__global__ void k_split(const float* __restrict__ s, __nv_bfloat16* __restrict__ hi,
                        __nv_bfloat16* __restrict__ lo, int n)
{
    for (int i = blockIdx.x * blockDim.x + threadIdx.x; i < n; i += gridDim.x * blockDim.x) {
        float v = s[i];
        __nv_bfloat16 h = __float2bfloat16(v);
        hi[i] = h;
        lo[i] = __float2bfloat16(v - __bfloat162float(h));
    }
}
__global__ void k_split_t(const float* __restrict__ src, __nv_bfloat16* __restrict__ hi,
                          __nv_bfloat16* __restrict__ lo, int K, int N)
{
    __shared__ float t[32][33];
    const int n0 = blockIdx.x << 5, k0 = blockIdx.y << 5;
    #pragma unroll
    for (int i = 0; i < 4; i++) {
        int r = threadIdx.y + i * 8;
        t[r][threadIdx.x] = src[(size_t)(k0 + r) * N + n0 + threadIdx.x];
    }
    __syncthreads();
    #pragma unroll
    for (int i = 0; i < 4; i++) {
        int c = threadIdx.y + i * 8;
        float v = t[threadIdx.x][c];
        __nv_bfloat16 h = __float2bfloat16(v);
        size_t o = (size_t)(n0 + c) * K + k0 + threadIdx.x;
        hi[o] = h;
        lo[o] = __float2bfloat16(v - __bfloat162float(h));
    }
}
// per-row amax quantize: src [R][1024] -> s8 + scale[r]=amax/127
template<typename T>
__global__ void k_quant_rows(const T* __restrict__ src, int8_t* __restrict__ dst,
                             float* __restrict__ scale)
{
    __shared__ float red[8];
    const int row = blockIdx.x;
    const T* s = src + (size_t)row * 1024;
    float v[4], am = 0.f;
    #pragma unroll
    for (int i = 0; i < 4; i++) {
        v[i] = (float)s[threadIdx.x + i * 256];
        am = fmaxf(am, fabsf(v[i]));
    }
    #pragma unroll
    for (int o = 16; o > 0; o >>= 1) am = fmaxf(am, __shfl_xor_sync(0xffffffffu, am, o));
    if ((threadIdx.x & 31) == 0) red[threadIdx.x >> 5] = am;
    __syncthreads();
    am = 0.f;
    #pragma unroll
    for (int q = 0; q < 8; q++) am = fmaxf(am, red[q]);
    const float sc = fmaxf(am, 1e-30f) * (1.f / 127.f);
    if (threadIdx.x == 0) scale[row] = sc;
    const float inv = 1.f / sc;
    #pragma unroll
    for (int i = 0; i < 4; i++) {
        int q = __float2int_rn(v[i] * inv);
        q = max(-127, min(127, q));
        dst[(size_t)row * 1024 + threadIdx.x + i * 256] = (int8_t)q;
    }
}
__global__ void k_colamax_init(int* svi) { if (threadIdx.x < HID) svi[threadIdx.x] = 0; }
// per-HID-column amax of mem_values [MEM][HID]
__global__ void k_colamax(const float* __restrict__ src, int* __restrict__ svi)
{
    __shared__ float cm[8][32];
    const int c = (blockIdx.x << 5) + threadIdx.x;
    const int r0 = blockIdx.y * 8192;
    float am = 0.f;
    for (int i = threadIdx.y; i < 8192; i += 8)
        am = fmaxf(am, fabsf(src[(size_t)(r0 + i) * HID + c]));
    cm[threadIdx.y][threadIdx.x] = am;
    __syncthreads();
    if (threadIdx.y == 0) {
        #pragma unroll
        for (int q = 1; q < 8; q++) am = fmaxf(am, cm[q][threadIdx.x]);
        atomicMax(svi + c, __float_as_int(am));
    }
}
// mem_values [MEM][HID] f32 -> MVT8 [HID][MEM] int8 (scale per HID col)
__global__ void k_transq_mv(const float* __restrict__ src, const int* __restrict__ svi,
                            int8_t* __restrict__ dst)
{
    __shared__ float t[32][33];
    const int r0 = blockIdx.y << 5;   // MEM
    const int c0 = blockIdx.x << 5;   // HID
    #pragma unroll
    for (int i = 0; i < 4; i++) {
        int r = threadIdx.y + i * 8;
        t[r][threadIdx.x] = src[(size_t)(r0 + r) * HID + c0 + threadIdx.x];
    }
    __syncthreads();
    #pragma unroll
    for (int i = 0; i < 4; i++) {
        int h = c0 + threadIdx.y + i * 8;
        float sc = fmaxf(__int_as_float(svi[h]), 1e-30f) * (1.f / 127.f);
        int q = __float2int_rn(t[threadIdx.x][threadIdx.y + i * 8] / sc);
        q = max(-127, min(127, q));
        dst[(size_t)h * MEM + r0 + threadIdx.x] = (int8_t)q;
    }
}
// rowmax from per-tile partials (one warp per row)
__global__ void k_maxreduce(const float* __restrict__ prs, float* __restrict__ mx)
{
    const int row = blockIdx.x * 8 + (threadIdx.x >> 5);
    const int lane = threadIdx.x & 31;
    float m = -1e30f;
    #pragma unroll
    for (int j = 0; j < NT_LOGITS / 32; j++)
        m = fmaxf(m, prs[(size_t)row * NT_LOGITS + lane + j * 32]);
    #pragma unroll
    for (int o = 16; o > 0; o >>= 1) m = fmaxf(m, __shfl_xor_sync(0xffffffffu, m, o));
    if (lane == 0) mx[row] = m;
}
// P8 = rn(127*exp(l - rowmax)); exact integer rowsum (deterministic).
// rs = sum(q) WITHOUT /127 -- pairs with gemm_i8<1>'s scl*(1/127) factor so the
// 127s cancel exactly in part/rs.
__global__ void k_softmax_quant(const __half* __restrict__ L, const float* __restrict__ mx,
                                int8_t* __restrict__ P8, float* __restrict__ rs)
{
    __shared__ int red[8];
    const int row = blockIdx.x;
    const float m = mx[row];
    const uint4* l4 = reinterpret_cast<const uint4*>(L + (size_t)row * MEM);
    uint2* p8 = reinterpret_cast<uint2*>(P8 + (size_t)row * MEM);
    int isum = 0;
    for (int i = threadIdx.x; i < MEM / 8; i += 256) {
        uint4 u = l4[i];
        uint32_t w[4] = {u.x, u.y, u.z, u.w};
        uint32_t qb[2] = {0, 0};
        #pragma unroll
        for (int j = 0; j < 4; j++) {
            float2 f = __half22float2(*reinterpret_cast<const __half2*>(&w[j]));
            int q0 = min(__float2int_rn(127.f * __expf(f.x - m)), 127);
            int q1 = min(__float2int_rn(127.f * __expf(f.y - m)), 127);
            isum += q0 + q1;
            qb[j >> 1] |= ((uint32_t)q0 << ((j & 1) * 16)) |
                          ((uint32_t)q1 << ((j & 1) * 16 + 8));
        }
        p8[i] = make_uint2(qb[0], qb[1]);
    }
    #pragma unroll
    for (int o = 16; o > 0; o >>= 1) isum += __shfl_xor_sync(0xffffffffu, isum, o);
    if ((threadIdx.x & 31) == 0) red[threadIdx.x >> 5] = isum;
    __syncthreads();
    if (threadIdx.x == 0) {
        int t = 0;
        #pragma unroll
        for (int q = 0; q < 8; q++) t += red[q];
        rs[row] = (float)t;          // exact integer sum; no 1/127 (see gemm_i8<1>)
    }
}
// combine split-K partials / rowsum -> combined[:, HID:]
__global__ void k_combine(const float* __restrict__ part, const float* __restrict__ rs,
                          __nv_bfloat16* __restrict__ ch, __nv_bfloat16* __restrict__ cl)
{
    const int i = blockIdx.x * 256 + threadIdx.x;
    const int e = i * 4;
    const int r = e >> 10;
    const int c = e & 1023;
    float4 a = make_float4(0.f, 0.f, 0.f, 0.f);
    #pragma unroll
    for (int s = 0; s < KSPLIT; s++) {
        const float4 v = *reinterpret_cast<const float4*>(part + (size_t)s * NQ * HID + e);
        a.x += v.x; a.y += v.y; a.z += v.z; a.w += v.w;
    }
    const float inv = 1.0f / rs[r];
    float v4[4] = {a.x * inv, a.y * inv, a.z * inv, a.w * inv};
    float lo[4];
    #pragma unroll
    for (int j = 0; j < 4; j++) {
        __nv_bfloat16 h = __float2bfloat16(v4[j]);
        lo[j] = v4[j] - __bfloat162float(h);
    }
    const size_t o = (size_t)r * (2 * HID) + HID + c;
    uint2 uh, ul;
    uh.x = pack_bf2(v4[0], v4[1]); uh.y = pack_bf2(v4[2], v4[3]);
    ul.x = pack_bf2(lo[0], lo[1]); ul.y = pack_bf2(lo[2], lo[3]);
    *reinterpret_cast<uint2*>(ch + o) = uh;
    *reinterpret_cast<uint2*>(cl + o) = ul;
}

// ---------------- launch ----------------
#define DEVPTR(name, sym, type) \
    type* name; { void* p_ = nullptr; cudaGetSymbolAddress(&p_, sym); name = (type*)p_; }

#define SMEM_SP 196608   // 4 stages x 48KB (bf16 split; epilogue 132KB fits)
#define SMEM_I8 147456   // 4 stages x 24KB; epilogue 135KB

extern "C" void kernel_launch(void* const* d_in, const int* in_sizes, int n_in,
                              void* d_out, int out_size)
{
    (void)in_sizes; (void)n_in; (void)out_size;
    const float* query = (const float*)d_in[0];
    const float* W_in  = (const float*)d_in[1];
    const float* b_in  = (const float*)d_in[2];
    const float* W_e1  = (const float*)d_in[3];
    const float* b_e1  = (const float*)d_in[4];
    const float* W_e2  = (const float*)d_in[5];
    const float* b_e2  = (const float*)d_in[6];
    const float* W_k   = (const float*)d_in[7];
    const float* b_k   = (const float*)d_in[8];
    const float* mem_keys   = (const float*)d_in[9];
    const float* mem_values = (const float*)d_in[10];
    const float* W_r1  = (const float*)d_in[11];
    const float* b_r1  = (const float*)d_in[12];
    const float* W_r2  = (const float*)d_in[13];
    const float* b_r2  = (const float*)d_in[14];
    float* out = (float*)d_out;

    DEVPTR(qh, g_qh, __nv_bfloat16)     DEVPTR(ql, g_ql, __nv_bfloat16)
    DEVPTR(Winh, g_Winh, __nv_bfloat16) DEVPTR(Winl, g_Winl, __nv_bfloat16)
    DEVPTR(We1h, g_We1h, __nv_bfloat16) DEVPTR(We1l, g_We1l, __nv_bfloat16)
    DEVPTR(We2h, g_We2h, __nv_bfloat16) DEVPTR(We2l, g_We2l, __nv_bfloat16)
    DEVPTR(Wkh, g_Wkh, __nv_bfloat16)   DEVPTR(Wkl, g_Wkl, __nv_bfloat16)
    DEVPTR(Wr1h, g_Wr1h, __nv_bfloat16) DEVPTR(Wr1l, g_Wr1l, __nv_bfloat16)
    DEVPTR(Wr2h, g_Wr2h, __nv_bfloat16) DEVPTR(Wr2l, g_Wr2l, __nv_bfloat16)
    DEVPTR(xh, g_xh, __nv_bfloat16)     DEVPTR(xl, g_xl, __nv_bfloat16)
    DEVPTR(hh, g_hh, __nv_bfloat16)     DEVPTR(hl, g_hl, __nv_bfloat16)
    DEVPTR(ch, g_ch, __nv_bfloat16)     DEVPTR(cl, g_cl, __nv_bfloat16)
    DEVPTR(key, g_key, __nv_bfloat16)
    DEVPTR(rh, g_rh, __nv_bfloat16)     DEVPTR(rl, g_rl, __nv_bfloat16)
    DEVPTR(key8, g_key8, int8_t)        DEVPTR(sk, g_sk, float)
    DEVPTR(MK8, g_MK8, int8_t)          DEVPTR(skb, g_skb, float)
    DEVPTR(MVT8, g_MVT8, int8_t)        DEVPTR(svi, g_svi, int)
    DEVPTR(L, g_L, __half)              DEVPTR(P8, g_P8, int8_t)
    DEVPTR(part, g_part, float)         DEVPTR(prs, g_prs, float)
    DEVPTR(rowmax, g_rowmax, float)     DEVPTR(rs, g_rs, float)

    cudaFuncSetAttribute(gemm_hmma<0>, cudaFuncAttributeMaxDynamicSharedMemorySize, SMEM_SP);
    cudaFuncSetAttribute(gemm_hmma<1>, cudaFuncAttributeMaxDynamicSharedMemorySize, SMEM_SP);
    cudaFuncSetAttribute(gemm_hmma<2>, cudaFuncAttributeMaxDynamicSharedMemorySize, SMEM_SP);
    cudaFuncSetAttribute(gemm_hmma<3>, cudaFuncAttributeMaxDynamicSharedMemorySize, SMEM_SP);
    cudaFuncSetAttribute(gemm_i8<0,false>, cudaFuncAttributeMaxDynamicSharedMemorySize, SMEM_I8);
    cudaFuncSetAttribute(gemm_i8<1,true>,  cudaFuncAttributeMaxDynamicSharedMemorySize, SMEM_I8);

    // ---- conversions / quantization of constants ----
    k_split<<<(NQ*EMB + 255) / 256, 256>>>(query, qh, ql, NQ*EMB);
    k_split_t<<<dim3(HID/32,  EMB/32),   dim3(32,8)>>>(W_in, Winh, Winl, EMB,   HID);
    k_split_t<<<dim3(2*HID/32, HID/32),  dim3(32,8)>>>(W_e1, We1h, We1l, HID,   2*HID);
    k_split_t<<<dim3(HID/32,  2*HID/32), dim3(32,8)>>>(W_e2, We2h, We2l, 2*HID, HID);
    k_split_t<<<dim3(HID/32,  HID/32),   dim3(32,8)>>>(W_k,  Wkh,  Wkl,  HID,   HID);
    k_split_t<<<dim3(2*HID/32, 2*HID/32),dim3(32,8)>>>(W_r1, Wr1h, Wr1l, 2*HID, 2*HID);
    k_split_t<<<dim3(EMB/32,  2*HID/32), dim3(32,8)>>>(W_r2, Wr2h, Wr2l, 2*HID, EMB);
    k_quant_rows<float><<<MEM, 256>>>(mem_keys, MK8, skb);
    k_colamax_init<<<1, HID>>>(svi);
    k_colamax<<<dim3(HID/32, MEM/8192), dim3(32,8)>>>(mem_values, svi);
    k_transq_mv<<<dim3(HID/32, MEM/32), dim3(32,8)>>>(mem_values, svi, MVT8);

    // ---- encoder chain (bf16 split) ----
    gemm_hmma<1><<<dim3(NQ/BM, HID/BN), 512, SMEM_SP>>>(
        qh, ql, Winh, Winl, b_in, nullptr, xh, xl, EMB, EMB, EMB, HID);
    gemm_hmma<2><<<dim3(NQ/BM, 2*HID/BN), 512, SMEM_SP>>>(
        xh, xl, We1h, We1l, b_e1, nullptr, hh, hl, HID, HID, HID, 2*HID);
    gemm_hmma<1><<<dim3(NQ/BM, HID/BN), 512, SMEM_SP>>>(
        hh, hl, We2h, We2l, b_e2, nullptr, ch, cl, 2*HID, 2*HID, 2*HID, 2*HID);
    gemm_hmma<3><<<dim3(NQ/BM, HID/BN), 512, SMEM_SP>>>(
        ch, cl, Wkh, Wkl, b_k, nullptr, key, nullptr, HID, 2*HID, HID, HID);

    // ---- attention (int8) ----
    k_quant_rows<__nv_bfloat16><<<NQ, 256>>>(key, key8, sk);
    // logits fp16 + rowmax partials; grid m-fastest (share streaming MK tiles)
    gemm_i8<0,false><<<dim3(NQ/BM, MEM/BN), 512, SMEM_I8>>>(
        key8, MK8, sk, skb, L, nullptr, prs, HID, HID, HID, MEM, 0);
    k_maxreduce<<<NQ/8, 256>>>(prs, rowmax);
    k_softmax_quant<<<NQ, 256>>>(L, rowmax, P8, rs);
    // retrieved partials: int8 split-K, n-fastest (share P tiles)
    gemm_i8<1,true><<<dim3(HID/BN, NQ/BM, KSPLIT), 512, SMEM_I8>>>(
        P8, MVT8, nullptr, reinterpret_cast<const float*>(svi), nullptr, part, nullptr,
        MEM/KSPLIT, MEM, MEM, HID, (size_t)NQ * HID);
    k_combine<<<NQ*HID/4/256, 256>>>(part, rs, ch, cl);

    // ---- retriever (bf16 split) ----
    gemm_hmma<2><<<dim3(NQ/BM, 2*HID/BN), 512, SMEM_SP>>>(
        ch, cl, Wr1h, Wr1l, b_r1, nullptr, rh, rl, 2*HID, 2*HID, 2*HID, 2*HID);
    gemm_hmma<0><<<dim3(NQ/BM, EMB/BN), 512, SMEM_SP>>>(
        rh, rl, Wr2h, Wr2l, b_r2, out, nullptr, nullptr, 2*HID, 2*HID, 2*HID, EMB);
}

// round 16
// speedup vs baseline: 2.3612x; 2.3612x over previous
#include <cuda_runtime.h>
#include <cuda_bf16.h>
#include <cstdint>
#include <cstddef>

#define NQ  4096
#define EMB 768
#define HID 1024
#define MEM 65536
#define KSPLIT 4
#define BM 128
#define BN 256
#define NT_LOGITS (MEM / BN)   // 256 n-tiles in logits GEMM

// ---------------- static device scratch ----------------
__device__ __nv_bfloat16 g_qh[NQ*EMB],        g_ql[NQ*EMB];
__device__ __nv_bfloat16 g_Winh[HID*EMB],     g_Winl[HID*EMB];      // weights transposed: [N][K]
__device__ __nv_bfloat16 g_We1h[2*HID*HID],   g_We1l[2*HID*HID];
__device__ __nv_bfloat16 g_We2h[HID*2*HID],   g_We2l[HID*2*HID];
__device__ __nv_bfloat16 g_Wkh[HID*HID],      g_Wkl[HID*HID];
__device__ __nv_bfloat16 g_Wr1h[2*HID*2*HID], g_Wr1l[2*HID*2*HID];
__device__ __nv_bfloat16 g_Wr2h[EMB*2*HID],   g_Wr2l[EMB*2*HID];
__device__ __nv_bfloat16 g_MK [(size_t)MEM*HID];    // mem_keys bf16 [MEM][HID]  (= [N][K])
__device__ __nv_bfloat16 g_MVT[(size_t)HID*MEM];    // mem_values^T [HID][MEM]   (= [N][K])
__device__ __nv_bfloat16 g_xh[NQ*HID],   g_xl[NQ*HID];
__device__ __nv_bfloat16 g_hh[NQ*2*HID], g_hl[NQ*2*HID];
__device__ __nv_bfloat16 g_ch[NQ*2*HID], g_cl[NQ*2*HID];   // combined = [encoded | retrieved]
__device__ __nv_bfloat16 g_key[NQ*HID];
__device__ __nv_bfloat16 g_P[(size_t)NQ*MEM];              // exp(logits/32) bf16
__device__ __nv_bfloat16 g_rh[NQ*2*HID], g_rl[NQ*2*HID];
__device__ float         g_part[(size_t)KSPLIT*NQ*HID];    // split-K partials
__device__ float         g_prs[(size_t)NQ*NT_LOGITS];      // per-tile rowsum partials
__device__ float         g_rowsum[NQ];

// ---------------- helpers ----------------
__device__ __forceinline__ void cpasync16(uint32_t saddr, const void* g) {
    asm volatile("cp.async.cg.shared.global [%0], [%1], 16;\n" :: "r"(saddr), "l"(g));
}
__device__ __forceinline__ void ldsm4(uint32_t* r, uint32_t addr) {
    asm volatile("ldmatrix.sync.aligned.m8n8.x4.shared.b16 {%0,%1,%2,%3}, [%4];\n"
        : "=r"(r[0]), "=r"(r[1]), "=r"(r[2]), "=r"(r[3]) : "r"(addr));
}
__device__ __forceinline__ void mma_bf16(float* c, const uint32_t* a, uint32_t b0, uint32_t b1) {
    asm volatile(
        "mma.sync.aligned.m16n8k16.row.col.f32.bf16.bf16.f32 "
        "{%0,%1,%2,%3}, {%4,%5,%6,%7}, {%8,%9}, {%0,%1,%2,%3};\n"
        : "+f"(c[0]), "+f"(c[1]), "+f"(c[2]), "+f"(c[3])
        : "r"(a[0]), "r"(a[1]), "r"(a[2]), "r"(a[3]), "r"(b0), "r"(b1));
}
__device__ __forceinline__ float gelu_erf(float x) {
    return 0.5f * x * (1.0f + erff(x * 0.70710678118654752f));
}
__device__ __forceinline__ uint32_t pack_bf2(float a, float b) {
    __nv_bfloat162 h; h.x = __float2bfloat16(a); h.y = __float2bfloat16(b);
    return *reinterpret_cast<uint32_t*>(&h);
}

// ======================= bf16 split HMMA GEMM (small main-path GEMMs) ===============
// C[M,N] = A[M,K] @ B[N,K]^T, 3-product hi/lo bf16 split, BK=32, 4 stages, 128x256 tile.
// EPI: 0 (+bias?)->f32 | 1 +bias->hi/lo bf16 | 2 +bias,gelu->hi/lo | 3 +bias->bf16
template<int EPI>
__global__ void __launch_bounds__(512, 1) gemm_hmma(
    const __nv_bfloat16* __restrict__ Ah, const __nv_bfloat16* __restrict__ Al,
    const __nv_bfloat16* __restrict__ Bh, const __nv_bfloat16* __restrict__ Bl,
    const float* __restrict__ bias,
    float* __restrict__ outF, __nv_bfloat16* __restrict__ outHi, __nv_bfloat16* __restrict__ outLo,
    int K, int lda, int ldb, int ldc)
{
    constexpr int NST = 4, PRE = 3, SST = 49152;
    extern __shared__ char smem[];
    const uint32_t sb = (uint32_t)__cvta_generic_to_shared(smem);
    const int tid = threadIdx.x;
    const int lane = tid & 31, wid = tid >> 5;
    const int wm = wid & 1, wn = wid >> 1;
    const int m0 = blockIdx.x * BM;
    const int n0 = blockIdx.y * BN;

    float acc[4][4][4];
    #pragma unroll
    for (int i = 0; i < 4; i++)
        #pragma unroll
        for (int j = 0; j < 4; j++)
            #pragma unroll
            for (int q = 0; q < 4; q++) acc[i][j][q] = 0.f;

    const int nkb = K >> 5;

    auto LOAD = [&](int st, int kb) {
        const uint32_t base = sb + st * SST;
        const size_t kg = (size_t)kb * 32;
        {
            int row = tid >> 2, c = tid & 3;
            uint32_t so = base + row * 64 + ((c ^ ((row >> 1) & 3)) << 4);
            const size_t go = (size_t)(m0 + row) * lda + kg + c * 8;
            cpasync16(so, Ah + go);
            cpasync16(so + 24576, Al + go);
        }
        #pragma unroll
        for (int i = 0; i < 2; i++) {
            int id = tid + i * 512;
            int row = id >> 2, c = id & 3;
            uint32_t so = base + 8192 + row * 64 + ((c ^ ((row >> 1) & 3)) << 4);
            const size_t go = (size_t)(n0 + row) * ldb + kg + c * 8;
            cpasync16(so, Bh + go);
            cpasync16(so + 24576, Bl + go);
        }
        asm volatile("cp.async.commit_group;" ::);
    };

    const int amat = lane >> 3;
    const int arow_l = (amat & 1) * 8 + (lane & 7);
    const int achv   = amat >> 1;
    const int brow_l = (amat >> 1) * 8 + (lane & 7);
    const int bchv   = amat & 1;

    auto COMPUTE = [&](int st) {
        const uint32_t ab = sb + st * SST;
        const uint32_t bb = ab + 8192;
        #pragma unroll
        for (int t = 0; t < 2; t++) {
            uint32_t ah[4][4], bh[2][4];
            #pragma unroll
            for (int mi = 0; mi < 4; mi++) {
                int row = wm * 64 + mi * 16 + arow_l;
                int ch = 2 * t + achv;
                ldsm4(ah[mi], ab + row * 64 + ((ch ^ ((row >> 1) & 3)) << 4));
            }
            #pragma unroll
            for (int nb = 0; nb < 2; nb++) {
                int row = wn * 32 + nb * 16 + brow_l;
                int ch = 2 * t + bchv;
                ldsm4(bh[nb], bb + row * 64 + ((ch ^ ((row >> 1) & 3)) << 4));
            }
            #pragma unroll
            for (int mi = 0; mi < 4; mi++)
                #pragma unroll
                for (int ni = 0; ni < 4; ni++)
                    mma_bf16(acc[mi][ni], ah[mi],
                             bh[ni >> 1][(ni & 1) * 2], bh[ni >> 1][(ni & 1) * 2 + 1]);
            {
                uint32_t al[4][4];
                #pragma unroll
                for (int mi = 0; mi < 4; mi++) {
                    int row = wm * 64 + mi * 16 + arow_l;
                    int ch = 2 * t + achv;
                    ldsm4(al[mi], ab + 24576 + row * 64 + ((ch ^ ((row >> 1) & 3)) << 4));
                }
                #pragma unroll
                for (int mi = 0; mi < 4; mi++)
                    #pragma unroll
                    for (int ni = 0; ni < 4; ni++)
                        mma_bf16(acc[mi][ni], al[mi],
                                 bh[ni >> 1][(ni & 1) * 2], bh[ni >> 1][(ni & 1) * 2 + 1]);
            }
            {
                uint32_t bl[2][4];
                #pragma unroll
                for (int nb = 0; nb < 2; nb++) {
                    int row = wn * 32 + nb * 16 + brow_l;
                    int ch = 2 * t + bchv;
                    ldsm4(bl[nb], bb + 24576 + row * 64 + ((ch ^ ((row >> 1) & 3)) << 4));
                }
                #pragma unroll
                for (int mi = 0; mi < 4; mi++)
                    #pragma unroll
                    for (int ni = 0; ni < 4; ni++)
                        mma_bf16(acc[mi][ni], ah[mi],
                                 bl[ni >> 1][(ni & 1) * 2], bl[ni >> 1][(ni & 1) * 2 + 1]);
            }
        }
    };

    #pragma unroll
    for (int i = 0; i < PRE; i++) LOAD(i, i);
    for (int kb = 0; kb < nkb; kb++) {
        const int pend = (nkb - kb < PRE) ? (nkb - kb) : PRE;
        if (pend == 3)      asm volatile("cp.async.wait_group 2;" ::: "memory");
        else if (pend == 2) asm volatile("cp.async.wait_group 1;" ::: "memory");
        else                asm volatile("cp.async.wait_group 0;" ::: "memory");
        __syncthreads();
        COMPUTE(kb % NST);
        if (kb + PRE < nkb) LOAD((kb + PRE) % NST, kb + PRE);
    }
    __syncthreads();

    // epilogue via SMEM stage
    float* smf = reinterpret_cast<float*>(smem);
    #pragma unroll
    for (int mi = 0; mi < 4; mi++)
        #pragma unroll
        for (int ni = 0; ni < 4; ni++) {
            int r = wm * 64 + mi * 16 + (lane >> 2);
            int cc = wn * 32 + ni * 8 + (lane & 3) * 2;
            smf[r * 258 + cc]           = acc[mi][ni][0];
            smf[r * 258 + cc + 1]       = acc[mi][ni][1];
            smf[(r + 8) * 258 + cc]     = acc[mi][ni][2];
            smf[(r + 8) * 258 + cc + 1] = acc[mi][ni][3];
        }
    __syncthreads();
    {
        const int r = tid & 127, sg = tid >> 7;
        const float* srow = smf + r * 258 + sg * 64;
        const int colbase = n0 + sg * 64;
        float v[64];
        #pragma unroll
        for (int j = 0; j < 64; j++) {
            float x = srow[j];
            if (EPI >= 1 || bias != nullptr) x += __ldg(bias + colbase + j);
            if (EPI == 2) x = gelu_erf(x);
            v[j] = x;
        }
        const size_t gb = (size_t)(m0 + r) * ldc + colbase;
        if (EPI == 0) {
            #pragma unroll
            for (int j = 0; j < 64; j += 4)
                *reinterpret_cast<float4*>(outF + gb + j) =
                    make_float4(v[j], v[j+1], v[j+2], v[j+3]);
        } else if (EPI == 3) {
            #pragma unroll
            for (int j = 0; j < 64; j += 8) {
                uint4 u;
                u.x = pack_bf2(v[j+0], v[j+1]); u.y = pack_bf2(v[j+2], v[j+3]);
                u.z = pack_bf2(v[j+4], v[j+5]); u.w = pack_bf2(v[j+6], v[j+7]);
                *reinterpret_cast<uint4*>(outHi + gb + j) = u;
            }
        } else {
            #pragma unroll
            for (int j = 0; j < 64; j += 8) {
                float lo[8];
                #pragma unroll
                for (int q = 0; q < 8; q++) {
                    __nv_bfloat16 hb = __float2bfloat16(v[j + q]);
                    lo[q] = v[j + q] - __bfloat162float(hb);
                }
                uint4 uh, ul;
                uh.x = pack_bf2(v[j+0], v[j+1]); uh.y = pack_bf2(v[j+2], v[j+3]);
                uh.z = pack_bf2(v[j+4], v[j+5]); uh.w = pack_bf2(v[j+6], v[j+7]);
                ul.x = pack_bf2(lo[0], lo[1]);   ul.y = pack_bf2(lo[2], lo[3]);
                ul.z = pack_bf2(lo[4], lo[5]);   ul.w = pack_bf2(lo[6], lo[7]);
                *reinterpret_cast<uint4*>(outHi + gb + j) = uh;
                *reinterpret_cast<uint4*>(outLo + gb + j) = ul;
            }
        }
    }
}

// ======================= big bf16 HMMA GEMM (attention GEMMs) =======================
// C[M,N] = A[M,K] @ B[N,K]^T, non-split bf16. CTA tile 128x256xBK64, 256 threads,
// warp grid 2x4, warp tile 64x64 (acc[4][8][4] = 128 regs). 3 stages x 48KB.
// LDS per k16 per CTA: 32KB (vs 48KB for the 16-warp 64x32 config).
// EPI 4: P = bf16(exp(acc*scale)) + per-tile rowsum partials (prs[row][ntile])
// EPI 0: f32 out (split-K partial; z = split index, out += z*zstride)
// SWAP: n-tile on blockIdx.x (fastest).
template<int EPI, bool SWAP>
__global__ void __launch_bounds__(256, 1) gemm_big(
    const __nv_bfloat16* __restrict__ A, const __nv_bfloat16* __restrict__ B,
    __nv_bfloat16* __restrict__ outHi, float* __restrict__ outF,
    float* __restrict__ prs, float scale,
    int K, int lda, int ldb, int ldc, size_t zstride)
{
    constexpr int NST = 3, PRE = 2, SST = 49152;   // [A 16K][B 32K] per stage
    extern __shared__ char smem[];
    const uint32_t sb = (uint32_t)__cvta_generic_to_shared(smem);
    const int tid = threadIdx.x;
    const int lane = tid & 31, wid = tid >> 5;
    const int wm = wid & 1, wn = wid >> 1;          // 2x4 warp grid, warp tile 64x64
    const int m0 = (SWAP ? blockIdx.y : blockIdx.x) * BM;
    const int n0 = (SWAP ? blockIdx.x : blockIdx.y) * BN;
    const int ntile = SWAP ? blockIdx.x : blockIdx.y;
    const size_t kz = (size_t)blockIdx.z * K;
    outF += (size_t)blockIdx.z * zstride;

    float acc[4][8][4];
    #pragma unroll
    for (int i = 0; i < 4; i++)
        #pragma unroll
        for (int j = 0; j < 8; j++)
            #pragma unroll
            for (int q = 0; q < 4; q++) acc[i][j][q] = 0.f;

    const int nkb = K >> 6;   // BK = 64

    auto LOAD = [&](int st, int kb) {
        const uint32_t base = sb + st * SST;
        const size_t kg = kz + (size_t)kb * 64;
        #pragma unroll
        for (int i = 0; i < 4; i++) {               // A: 128 rows x 8 chunks of 16B
            int id = tid + i * 256;
            int row = id >> 3, c = id & 7;
            uint32_t so = base + row * 128 + ((c ^ (row & 7)) << 4);
            cpasync16(so, A + (size_t)(m0 + row) * lda + kg + c * 8);
        }
        #pragma unroll
        for (int i = 0; i < 8; i++) {               // B: 256 rows x 8 chunks
            int id = tid + i * 256;
            int row = id >> 3, c = id & 7;
            uint32_t so = base + 16384 + row * 128 + ((c ^ (row & 7)) << 4);
            cpasync16(so, B + (size_t)(n0 + row) * ldb + kg + c * 8);
        }
        asm volatile("cp.async.commit_group;" ::);
    };

    const int amat = lane >> 3;
    const int arow_l = (amat & 1) * 8 + (lane & 7);
    const int achv   = amat >> 1;
    const int brow_l = (amat >> 1) * 8 + (lane & 7);
    const int bchv   = amat & 1;

    auto COMPUTE = [&](int st) {
        const uint32_t ab = sb + st * SST;
        const uint32_t bb = ab + 16384;
        #pragma unroll
        for (int t = 0; t < 4; t++) {               // four k16 steps per BK64
            uint32_t a[4][4], b[4][4];
            #pragma unroll
            for (int mi = 0; mi < 4; mi++) {
                int row = wm * 64 + mi * 16 + arow_l;
                int ch = 2 * t + achv;
                ldsm4(a[mi], ab + row * 128 + ((ch ^ (row & 7)) << 4));
            }
            #pragma unroll
            for (int nb = 0; nb < 4; nb++) {
                int row = wn * 64 + nb * 16 + brow_l;
                int ch = 2 * t + bchv;
                ldsm4(b[nb], bb + row * 128 + ((ch ^ (row & 7)) << 4));
            }
            #pragma unroll
            for (int mi = 0; mi < 4; mi++)
                #pragma unroll
                for (int ni = 0; ni < 8; ni++)
                    mma_bf16(acc[mi][ni], a[mi],
                             b[ni >> 1][(ni & 1) * 2], b[ni >> 1][(ni & 1) * 2 + 1]);
        }
    };

    #pragma unroll
    for (int i = 0; i < PRE; i++) LOAD(i, i);
    for (int kb = 0; kb < nkb; kb++) {
        const int pend = (nkb - kb < PRE) ? (nkb - kb) : PRE;
        if (pend == 2) asm volatile("cp.async.wait_group 1;" ::: "memory");
        else           asm volatile("cp.async.wait_group 0;" ::: "memory");
        __syncthreads();
        COMPUTE(kb % NST);
        if (kb + PRE < nkb) LOAD((kb + PRE) % NST, kb + PRE);
    }
    __syncthreads();

    // -------- epilogue: full 128x256 fp32 tile through SMEM --------
    float* smf = reinterpret_cast<float*>(smem);
    float* redbuf = smf + 128 * 258;                 // 256 floats
    #pragma unroll
    for (int mi = 0; mi < 4; mi++)
        #pragma unroll
        for (int ni = 0; ni < 8; ni++) {
            int r = wm * 64 + mi * 16 + (lane >> 2);
            int cc = wn * 64 + ni * 8 + (lane & 3) * 2;
            smf[r * 258 + cc]           = acc[mi][ni][0];
            smf[r * 258 + cc + 1]       = acc[mi][ni][1];
            smf[(r + 8) * 258 + cc]     = acc[mi][ni][2];
            smf[(r + 8) * 258 + cc + 1] = acc[mi][ni][3];
        }
    __syncthreads();
    {
        const int r = tid >> 1, sg = tid & 1;        // 2 threads/row, 128 cols each
        const float* srow = smf + r * 258 + sg * 128;
        const int rowg = m0 + r;
        const size_t gb = (size_t)rowg * ldc + n0 + sg * 128;
        if (EPI == 4) {
            float rsum = 0.f;
            #pragma unroll 4
            for (int j = 0; j < 128; j += 8) {
                float vv[8];
                #pragma unroll
                for (int q = 0; q < 8; q++) {
                    float x = __expf(srow[j + q] * scale);
                    x = __bfloat162float(__float2bfloat16(x));   // match stored P
                    rsum += x;
                    vv[q] = x;
                }
                uint4 u;
                u.x = pack_bf2(vv[0], vv[1]); u.y = pack_bf2(vv[2], vv[3]);
                u.z = pack_bf2(vv[4], vv[5]); u.w = pack_bf2(vv[6], vv[7]);
                *reinterpret_cast<uint4*>(outHi + gb + j) = u;
            }
            redbuf[sg * 128 + r] = rsum;
        } else {
            #pragma unroll 8
            for (int j = 0; j < 128; j += 4)
                *reinterpret_cast<float4*>(outF + gb + j) =
                    make_float4(srow[j], srow[j+1], srow[j+2], srow[j+3]);
        }
    }
    if (EPI == 4) {
        __syncthreads();
        if (tid < 128) {
            float s = redbuf[tid] + redbuf[128 + tid];
            prs[(size_t)(m0 + tid) * NT_LOGITS + ntile] = s;
        }
    }
}

// ---------------- conversion / reduction kernels ----------------
__global__ void k_split(const float* __restrict__ s, __nv_bfloat16* __restrict__ hi,
                        __nv_bfloat16* __restrict__ lo, int n)
{
    for (int i = blockIdx.x * blockDim.x + threadIdx.x; i < n; i += gridDim.x * blockDim.x) {
        float v = s[i];
        __nv_bfloat16 h = __float2bfloat16(v);
        hi[i] = h;
        lo[i] = __float2bfloat16(v - __bfloat162float(h));
    }
}
// src [K][N] f32 -> hi/lo [N][K] bf16 (transposed split for [N][K] B operand)
__global__ void k_split_t(const float* __restrict__ src, __nv_bfloat16* __restrict__ hi,
                          __nv_bfloat16* __restrict__ lo, int K, int N)
{
    __shared__ float t[32][33];
    const int n0 = blockIdx.x << 5, k0 = blockIdx.y << 5;
    #pragma unroll
    for (int i = 0; i < 4; i++) {
        int r = threadIdx.y + i * 8;
        t[r][threadIdx.x] = src[(size_t)(k0 + r) * N + n0 + threadIdx.x];
    }
    __syncthreads();
    #pragma unroll
    for (int i = 0; i < 4; i++) {
        int c = threadIdx.y + i * 8;
        float v = t[threadIdx.x][c];
        __nv_bfloat16 h = __float2bfloat16(v);
        size_t o = (size_t)(n0 + c) * K + k0 + threadIdx.x;
        hi[o] = h;
        lo[o] = __float2bfloat16(v - __bfloat162float(h));
    }
}
__global__ void k_tobf16(const float* __restrict__ s, __nv_bfloat16* __restrict__ d, size_t n)
{
    for (size_t i = blockIdx.x * (size_t)blockDim.x + threadIdx.x; i < n;
         i += (size_t)gridDim.x * blockDim.x)
        d[i] = __float2bfloat16(s[i]);
}
// mem_values [MEM][HID] f32 -> g_MVT [HID][MEM] bf16
__global__ void k_transpose_bf16(const float* __restrict__ src, __nv_bfloat16* __restrict__ dst)
{
    __shared__ __nv_bfloat16 tile[32][33];
    const int r0 = blockIdx.y << 5;   // MEM base
    const int c0 = blockIdx.x << 5;   // HID base
    #pragma unroll
    for (int i = 0; i < 4; i++) {
        int r = threadIdx.y + i * 8;
        tile[r][threadIdx.x] = __float2bfloat16(src[(size_t)(r0 + r) * HID + c0 + threadIdx.x]);
    }
    __syncthreads();
    #pragma unroll
    for (int i = 0; i < 4; i++) {
        int c = threadIdx.y + i * 8;
        dst[(size_t)(c0 + c) * MEM + r0 + threadIdx.x] = tile[threadIdx.x][c];
    }
}
// rowsum from per-tile partials: one warp per row (deterministic)
__global__ void k_rsreduce(const float* __restrict__ prs, float* __restrict__ rs)
{
    const int row = blockIdx.x * 8 + (threadIdx.x >> 5);
    const int lane = threadIdx.x & 31;
    float s = 0.f;
    #pragma unroll
    for (int j = 0; j < NT_LOGITS / 32; j++)
        s += prs[(size_t)row * NT_LOGITS + lane + j * 32];
    #pragma unroll
    for (int o = 16; o > 0; o >>= 1) s += __shfl_xor_sync(0xffffffffu, s, o);
    if (lane == 0) rs[row] = s;
}
// combine split-K partials, scale by 1/rowsum, write retrieved into combined[:, HID:]
__global__ void k_combine(const float* __restrict__ part, const float* __restrict__ rs,
                          __nv_bfloat16* __restrict__ ch, __nv_bfloat16* __restrict__ cl)
{
    const int i = blockIdx.x * 256 + threadIdx.x;   // float4 index
    const int e = i * 4;
    const int r = e >> 10;
    const int c = e & 1023;
    float4 a = make_float4(0.f, 0.f, 0.f, 0.f);
    #pragma unroll
    for (int s = 0; s < KSPLIT; s++) {
        const float4 v = *reinterpret_cast<const float4*>(part + (size_t)s * NQ * HID + e);
        a.x += v.x; a.y += v.y; a.z += v.z; a.w += v.w;
    }
    const float inv = 1.0f / rs[r];
    float v4[4] = {a.x * inv, a.y * inv, a.z * inv, a.w * inv};
    float lo[4];
    #pragma unroll
    for (int j = 0; j < 4; j++) {
        __nv_bfloat16 h = __float2bfloat16(v4[j]);
        lo[j] = v4[j] - __bfloat162float(h);
    }
    const size_t o = (size_t)r * (2 * HID) + HID + c;
    uint2 uh, ul;
    uh.x = pack_bf2(v4[0], v4[1]); uh.y = pack_bf2(v4[2], v4[3]);
    ul.x = pack_bf2(lo[0], lo[1]); ul.y = pack_bf2(lo[2], lo[3]);
    *reinterpret_cast<uint2*>(ch + o) = uh;
    *reinterpret_cast<uint2*>(cl + o) = ul;
}

// ---------------- launch ----------------
#define DEVPTR(name, sym, type) \
    type* name; { void* p_ = nullptr; cudaGetSymbolAddress(&p_, sym); name = (type*)p_; }

#define SMEM_SP  196608   // 4 stages x 48KB (split small GEMMs; epilogue 132KB fits)
#define SMEM_BIG 147456   // 3 stages x 48KB (big GEMMs; epilogue 133KB fits)

extern "C" void kernel_launch(void* const* d_in, const int* in_sizes, int n_in,
                              void* d_out, int out_size)
{
    (void)in_sizes; (void)n_in; (void)out_size;
    const float* query = (const float*)d_in[0];
    const float* W_in  = (const float*)d_in[1];
    const float* b_in  = (const float*)d_in[2];
    const float* W_e1  = (const float*)d_in[3];
    const float* b_e1  = (const float*)d_in[4];
    const float* W_e2  = (const float*)d_in[5];
    const float* b_e2  = (const float*)d_in[6];
    const float* W_k   = (const float*)d_in[7];
    const float* b_k   = (const float*)d_in[8];
    const float* mem_keys   = (const float*)d_in[9];
    const float* mem_values = (const float*)d_in[10];
    const float* W_r1  = (const float*)d_in[11];
    const float* b_r1  = (const float*)d_in[12];
    const float* W_r2  = (const float*)d_in[13];
    const float* b_r2  = (const float*)d_in[14];
    float* out = (float*)d_out;

    DEVPTR(qh, g_qh, __nv_bfloat16)     DEVPTR(ql, g_ql, __nv_bfloat16)
    DEVPTR(Winh, g_Winh, __nv_bfloat16) DEVPTR(Winl, g_Winl, __nv_bfloat16)
    DEVPTR(We1h, g_We1h, __nv_bfloat16) DEVPTR(We1l, g_We1l, __nv_bfloat16)
    DEVPTR(We2h, g_We2h, __nv_bfloat16) DEVPTR(We2l, g_We2l, __nv_bfloat16)
    DEVPTR(Wkh, g_Wkh, __nv_bfloat16)   DEVPTR(Wkl, g_Wkl, __nv_bfloat16)
    DEVPTR(Wr1h, g_Wr1h, __nv_bfloat16) DEVPTR(Wr1l, g_Wr1l, __nv_bfloat16)
    DEVPTR(Wr2h, g_Wr2h, __nv_bfloat16) DEVPTR(Wr2l, g_Wr2l, __nv_bfloat16)
    DEVPTR(MK, g_MK, __nv_bfloat16)     DEVPTR(MVT, g_MVT, __nv_bfloat16)
    DEVPTR(xh, g_xh, __nv_bfloat16)     DEVPTR(xl, g_xl, __nv_bfloat16)
    DEVPTR(hh, g_hh, __nv_bfloat16)     DEVPTR(hl, g_hl, __nv_bfloat16)
    DEVPTR(ch, g_ch, __nv_bfloat16)     DEVPTR(cl, g_cl, __nv_bfloat16)
    DEVPTR(key, g_key, __nv_bfloat16)
    DEVPTR(P, g_P, __nv_bfloat16)
    DEVPTR(rh, g_rh, __nv_bfloat16)     DEVPTR(rl, g_rl, __nv_bfloat16)
    DEVPTR(part, g_part, float)
    DEVPTR(prs, g_prs, float)
    DEVPTR(rowsum, g_rowsum, float)

    cudaFuncSetAttribute(gemm_hmma<0>, cudaFuncAttributeMaxDynamicSharedMemorySize, SMEM_SP);
    cudaFuncSetAttribute(gemm_hmma<1>, cudaFuncAttributeMaxDynamicSharedMemorySize, SMEM_SP);
    cudaFuncSetAttribute(gemm_hmma<2>, cudaFuncAttributeMaxDynamicSharedMemorySize, SMEM_SP);
    cudaFuncSetAttribute(gemm_hmma<3>, cudaFuncAttributeMaxDynamicSharedMemorySize, SMEM_SP);
    cudaFuncSetAttribute(gemm_big<4,false>, cudaFuncAttributeMaxDynamicSharedMemorySize, SMEM_BIG);
    cudaFuncSetAttribute(gemm_big<0,true>,  cudaFuncAttributeMaxDynamicSharedMemorySize, SMEM_BIG);

    // ---- conversions ----
    k_split<<<(NQ*EMB + 255) / 256, 256>>>(query, qh, ql, NQ*EMB);
    k_split_t<<<dim3(HID/32,  EMB/32),   dim3(32,8)>>>(W_in, Winh, Winl, EMB,   HID);
    k_split_t<<<dim3(2*HID/32, HID/32),  dim3(32,8)>>>(W_e1, We1h, We1l, HID,   2*HID);
    k_split_t<<<dim3(HID/32,  2*HID/32), dim3(32,8)>>>(W_e2, We2h, We2l, 2*HID, HID);
    k_split_t<<<dim3(HID/32,  HID/32),   dim3(32,8)>>>(W_k,  Wkh,  Wkl,  HID,   HID);
    k_split_t<<<dim3(2*HID/32, 2*HID/32),dim3(32,8)>>>(W_r1, Wr1h, Wr1l, 2*HID, 2*HID);
    k_split_t<<<dim3(EMB/32,  2*HID/32), dim3(32,8)>>>(W_r2, Wr2h, Wr2l, 2*HID, EMB);
    k_tobf16<<<8192, 256>>>(mem_keys, MK, (size_t)MEM * HID);
    k_transpose_bf16<<<dim3(HID/32, MEM/32), dim3(32, 8)>>>(mem_values, MVT);

    // ---- encoder chain (bf16 split, 128x256) ----
    gemm_hmma<1><<<dim3(NQ/BM, HID/BN), 512, SMEM_SP>>>(
        qh, ql, Winh, Winl, b_in, nullptr, xh, xl, EMB, EMB, EMB, HID);
    gemm_hmma<2><<<dim3(NQ/BM, 2*HID/BN), 512, SMEM_SP>>>(
        xh, xl, We1h, We1l, b_e1, nullptr, hh, hl, HID, HID, HID, 2*HID);
    gemm_hmma<1><<<dim3(NQ/BM, HID/BN), 512, SMEM_SP>>>(
        hh, hl, We2h, We2l, b_e2, nullptr, ch, cl, 2*HID, 2*HID, 2*HID, 2*HID);
    gemm_hmma<3><<<dim3(NQ/BM, HID/BN), 512, SMEM_SP>>>(
        ch, cl, Wkh, Wkl, b_k, nullptr, key, nullptr, HID, 2*HID, HID, HID);

    // ---- attention (bf16, 128x256 / 8-warp 64x64 big kernel) ----
    // P = exp((key @ mem_keys^T)/32) bf16 + fused rowsum partials; m-fastest grid
    gemm_big<4,false><<<dim3(NQ/BM, MEM/BN), 256, SMEM_BIG>>>(
        key, MK, P, nullptr, prs, 0.03125f, HID, HID, HID, MEM, 0);
    k_rsreduce<<<NQ/8, 256>>>(prs, rowsum);
    // retrieved partials: split-K over MEM; n-fastest grid (share P tiles)
    gemm_big<0,true><<<dim3(HID/BN, NQ/BM, KSPLIT), 256, SMEM_BIG>>>(
        P, MVT, nullptr, part, nullptr, 0.f, MEM/KSPLIT, MEM, MEM, HID, (size_t)NQ * HID);
    k_combine<<<NQ*HID/4/256, 256>>>(part, rowsum, ch, cl);

    // ---- retriever (bf16 split) ----
    gemm_hmma<2><<<dim3(NQ/BM, 2*HID/BN), 512, SMEM_SP>>>(
        ch, cl, Wr1h, Wr1l, b_r1, nullptr, rh, rl, 2*HID, 2*HID, 2*HID, 2*HID);
    gemm_hmma<0><<<dim3(NQ/BM, EMB/BN), 512, SMEM_SP>>>(
        rh, rl, Wr2h, Wr2l, b_r2, out, nullptr, nullptr, 2*HID, 2*HID, 2*HID, EMB);
}